// round 1
// baseline (speedup 1.0000x reference)
#include <cuda_runtime.h>
#include <cuda_bf16.h>
#include <math.h>

// Problem constants (hardcoded from setup_inputs):
//  x: [16, 512, 64, 64] fp32 == [64 batches][128 ch][4096 pix] contiguous
//  Ci = 128, N = 4096, 64 folded batches.
#define NB     64
#define CI     128
#define NPIX   4096
#define KSPLIT 8
#define KCHUNK (NPIX / KSPLIT)   // 512
#define PAD    132               // 128 + 4 padding for smem matrices

// ---------------- scratch (no allocations allowed) ----------------
__device__ float g_Gpart[NB * KSPLIT * CI * CI];   // 33.5 MB partial Grams
__device__ float g_spart[NB * KSPLIT * CI];        // partial row sums
__device__ float g_A[NB * CI * CI];                // folded matrix A'' (incl. +I)
__device__ float g_bvec[NB * CI];                  // folded bias b'

// =====================================================================
// Kernel 1: partial Gram  G_part[bb,ks] = X[bb][:, ksrange] X^T, + rowsums
// grid (KSPLIT, NB), 256 threads, 8x8 microtile over the 128x128 output
// =====================================================================
__global__ void __launch_bounds__(256, 2)
gram_kernel(const float* __restrict__ X)
{
    const int ks = blockIdx.x;
    const int bb = blockIdx.y;
    const float* Xb = X + (size_t)bb * CI * NPIX + ks * KCHUNK;

    __shared__ float sXT[32][PAD];   // [k within chunk][channel]

    const int t  = threadIdx.x;
    const int tr = (t >> 4) << 3;    // output row base (0..120)
    const int tc = (t & 15) << 3;    // output col base

    const int lc   = t >> 1;         // loader: channel row 0..127
    const int lseg = (t & 1) * 16;   // loader: 16-col segment

    float acc[8][8];
#pragma unroll
    for (int i = 0; i < 8; i++)
#pragma unroll
        for (int j = 0; j < 8; j++) acc[i][j] = 0.f;
    float srow[8] = {0.f, 0.f, 0.f, 0.f, 0.f, 0.f, 0.f, 0.f};

    for (int ch = 0; ch < KCHUNK / 32; ++ch) {
        // load 128 x 32 column chunk (each thread 16 consecutive floats)
        const float4* src = (const float4*)(Xb + (size_t)lc * NPIX + ch * 32 + lseg);
        float4 v0 = src[0], v1 = src[1], v2 = src[2], v3 = src[3];
        float buf[16];
        *(float4*)(buf + 0)  = v0;
        *(float4*)(buf + 4)  = v1;
        *(float4*)(buf + 8)  = v2;
        *(float4*)(buf + 12) = v3;

        __syncthreads();   // previous chunk's compute done
#pragma unroll
        for (int q = 0; q < 16; q++) sXT[lseg + q][lc] = buf[q];
        __syncthreads();

#pragma unroll 4
        for (int k = 0; k < 32; k++) {
            float4 a0 = *(const float4*)&sXT[k][tr];
            float4 a1 = *(const float4*)&sXT[k][tr + 4];
            float4 b0 = *(const float4*)&sXT[k][tc];
            float4 b1 = *(const float4*)&sXT[k][tc + 4];
            float a[8] = {a0.x, a0.y, a0.z, a0.w, a1.x, a1.y, a1.z, a1.w};
            float b[8] = {b0.x, b0.y, b0.z, b0.w, b1.x, b1.y, b1.z, b1.w};
#pragma unroll
            for (int i = 0; i < 8; i++)
#pragma unroll
                for (int j = 0; j < 8; j++) acc[i][j] += a[i] * b[j];
            if ((t & 15) == 0) {
#pragma unroll
                for (int i = 0; i < 8; i++) srow[i] += a[i];
            }
        }
    }

    float* P = g_Gpart + ((size_t)(bb * KSPLIT + ks)) * CI * CI;
#pragma unroll
    for (int i = 0; i < 8; i++)
#pragma unroll
        for (int j = 0; j < 8; j++)
            P[(tr + i) * CI + tc + j] = acc[i][j];
    if ((t & 15) == 0) {
#pragma unroll
        for (int i = 0; i < 8; i++)
            g_spart[(bb * KSPLIT + ks) * CI + tr + i] = srow[i];
    }
}

// =====================================================================
// Kernel 2: per-batch chain of 128x128 GEMMs + softmax, folding into A'', b'
// 64 CTAs, 256 threads, 3 dynamic-smem 128xPAD buffers (≈198 KB)
// Convention: buffers hold M[e][i] at M[e*PAD + i]; micro-GEMM computes
//             W[i][j] = sum_e U[e][i]*V[e][j], stored O[i*PAD + j].
// =====================================================================
__device__ __forceinline__ void mg128(const float* U, const float* V,
                                      float* O, int t)
{
    const int tr = (t >> 4) << 3;
    const int tc = (t & 15) << 3;
    float acc[8][8];
#pragma unroll
    for (int i = 0; i < 8; i++)
#pragma unroll
        for (int j = 0; j < 8; j++) acc[i][j] = 0.f;

#pragma unroll 4
    for (int e = 0; e < 128; e++) {
        float4 a0 = *(const float4*)(U + e * PAD + tr);
        float4 a1 = *(const float4*)(U + e * PAD + tr + 4);
        float4 b0 = *(const float4*)(V + e * PAD + tc);
        float4 b1 = *(const float4*)(V + e * PAD + tc + 4);
        float a[8] = {a0.x, a0.y, a0.z, a0.w, a1.x, a1.y, a1.z, a1.w};
        float b[8] = {b0.x, b0.y, b0.z, b0.w, b1.x, b1.y, b1.z, b1.w};
#pragma unroll
        for (int i = 0; i < 8; i++)
#pragma unroll
            for (int j = 0; j < 8; j++) acc[i][j] += a[i] * b[j];
    }
#pragma unroll
    for (int i = 0; i < 8; i++)
#pragma unroll
        for (int j = 0; j < 8; j++)
            O[(tr + i) * PAD + (tc + j)] = acc[i][j];
}

__device__ __forceinline__ void mg128_final(const float* U, const float* V,
                                            float* gout, const float* scale, int t)
{
    const int tr = (t >> 4) << 3;
    const int tc = (t & 15) << 3;
    float acc[8][8];
#pragma unroll
    for (int i = 0; i < 8; i++)
#pragma unroll
        for (int j = 0; j < 8; j++) acc[i][j] = 0.f;

#pragma unroll 4
    for (int e = 0; e < 128; e++) {
        float4 a0 = *(const float4*)(U + e * PAD + tr);
        float4 a1 = *(const float4*)(U + e * PAD + tr + 4);
        float4 b0 = *(const float4*)(V + e * PAD + tc);
        float4 b1 = *(const float4*)(V + e * PAD + tc + 4);
        float a[8] = {a0.x, a0.y, a0.z, a0.w, a1.x, a1.y, a1.z, a1.w};
        float b[8] = {b0.x, b0.y, b0.z, b0.w, b1.x, b1.y, b1.z, b1.w};
#pragma unroll
        for (int i = 0; i < 8; i++)
#pragma unroll
            for (int j = 0; j < 8; j++) acc[i][j] += a[i] * b[j];
    }
#pragma unroll
    for (int i = 0; i < 8; i++) {
        float sc = scale[tr + i];
#pragma unroll
        for (int j = 0; j < 8; j++) {
            int r = tr + i, c = tc + j;
            gout[r * CI + c] = sc * acc[i][j] + ((r == c) ? 1.0f : 0.0f);
        }
    }
}

__global__ void __launch_bounds__(256)
chain_kernel(const float* __restrict__ theta_w, const float* __restrict__ theta_b,
             const float* __restrict__ phi_w,   const float* __restrict__ phi_b,
             const float* __restrict__ g_w,     const float* __restrict__ g_b,
             const float* __restrict__ W_w,     const float* __restrict__ W_b,
             const float* __restrict__ bn_gamma, const float* __restrict__ bn_beta,
             const float* __restrict__ bn_mean,  const float* __restrict__ bn_var)
{
    extern __shared__ float dsm[];
    float* B0 = dsm;
    float* B1 = dsm + CI * PAD;
    float* B2 = dsm + 2 * CI * PAD;

    __shared__ float sv_s[CI], sv_u[CI], sv_q[CI], sv_tb[CI],
                     sv_gb[CI], sv_c[CI], sv_scale[CI];

    const int t  = threadIdx.x;
    const int bb = blockIdx.x;

    // --- stage G (reduced partials; symmetric so natural layout works) ---
    const float* Gp = g_Gpart + (size_t)bb * KSPLIT * CI * CI;
    for (int idx = t; idx < CI * CI; idx += 256) {
        float v = 0.f;
#pragma unroll
        for (int ks = 0; ks < KSPLIT; ks++) v += Gp[ks * CI * CI + idx];
        B0[(idx >> 7) * PAD + (idx & 127)] = v;
    }
    if (t < CI) {
        float v = 0.f;
#pragma unroll
        for (int ks = 0; ks < KSPLIT; ks++) v += g_spart[(bb * KSPLIT + ks) * CI + t];
        sv_s[t]  = v;
        sv_tb[t] = theta_b[t];
        sv_gb[t] = g_b[t];
        sv_scale[t] = bn_gamma[t] * rsqrtf(bn_var[t] + 1e-5f);
    }
    // --- stage theta^T into B1 ---
    for (int idx = t; idx < CI * CI; idx += 256) {
        int r = idx >> 7, c = idx & 127;
        B1[c * PAD + r] = theta_w[idx];
    }
    __syncthreads();

    // v[d] = (theta_w s)[d];  q[d] = v[d] + N*theta_b[d]
    if (t < CI) {
        float v = 0.f;
#pragma unroll 8
        for (int e = 0; e < 128; e++) v += B1[e * PAD + t] * sv_s[e];
        sv_q[t] = v + 4096.0f * sv_tb[t];
    }
    __syncthreads();

    // step1: T1 = G theta^T   -> B2
    mg128(B0, B1, B2, t);
    __syncthreads();

    // stage phi^T into B0
    for (int idx = t; idx < CI * CI; idx += 256) {
        int r = idx >> 7, c = idx & 127;
        B0[c * PAD + r] = phi_w[idx];
    }
    __syncthreads();
    // u[c] = (phi_w s)[c]
    if (t < CI) {
        float v = 0.f;
#pragma unroll 8
        for (int e = 0; e < 128; e++) v += B0[e * PAD + t] * sv_s[e];
        sv_u[t] = v;
    }
    __syncthreads();

    // step2: L = phi T1  -> B1
    mg128(B0, B2, B1, t);
    __syncthreads();

    // softmax rows with rank-1 logit terms; write f^T into B2, cvec = f g_b
    if (t < CI) {
        float w1 = sv_u[t];      // * theta_b[d]
        float w2 = phi_b[t];     // * (v[d] + N theta_b[d])
        float* row = B1 + t * PAD;
        float mx = -1e30f;
#pragma unroll 8
        for (int d = 0; d < 128; d++) {
            float v = row[d] + w1 * sv_tb[d] + w2 * sv_q[d];
            row[d] = v;
            mx = fmaxf(mx, v);
        }
        float ssum = 0.f;
#pragma unroll 8
        for (int d = 0; d < 128; d++) {
            float ev = expf(row[d] - mx);
            row[d] = ev;
            ssum += ev;
        }
        float inv = 1.0f / ssum;
        float cacc = 0.f;
#pragma unroll 8
        for (int d = 0; d < 128; d++) {
            float f = row[d] * inv;
            B2[d * PAD + t] = f;           // f^T: buffer[e=d][i=row c]
            cacc += f * sv_gb[d];
        }
        sv_c[t] = cacc;
    }
    __syncthreads();

    // stage g_w natural into B0
    for (int idx = t; idx < CI * CI; idx += 256)
        B0[(idx >> 7) * PAD + (idx & 127)] = g_w[idx];
    __syncthreads();

    // step4: M = f g_w  -> B1
    mg128(B2, B0, B1, t);
    __syncthreads();

    // stage W_w^T into B2
    for (int idx = t; idx < CI * CI; idx += 256) {
        int r = idx >> 7, c = idx & 127;
        B2[c * PAD + r] = W_w[idx];
    }
    __syncthreads();

    // bias: b' = scale*(W_w cvec + W_b) + (beta - mean*scale)
    if (t < CI) {
        float b0 = 0.f;
#pragma unroll 8
        for (int e = 0; e < 128; e++) b0 += B2[e * PAD + t] * sv_c[e];
        float sc = sv_scale[t];
        g_bvec[bb * CI + t] = sc * (b0 + W_b[t]) + bn_beta[t] - bn_mean[t] * sc;
    }

    // step5: A'' = diag(scale) * (W_w M) + I  -> global
    mg128_final(B2, B1, g_A + (size_t)bb * CI * CI, sv_scale, t);
}

// =====================================================================
// Kernel 3: Z = A'' X + b' 1^T   (residual + BN + W-conv all folded)
// grid (16, 64), 512 threads, 128x256 output tile, 8x8 microtiles
// =====================================================================
__global__ void __launch_bounds__(512)
apply_kernel(const float* __restrict__ X, float* __restrict__ Z)
{
    const int bb = blockIdx.y;
    const int n0 = blockIdx.x * 256;

    __shared__ float sAT[16][PAD];   // A''^T chunk: [k][r]
    __shared__ float sX[16][260];    // X chunk:     [k][n]

    const int t   = threadIdx.x;
    const int tr  = (t >> 5) << 3;   // 16 thread-rows
    const int tcn = (t & 31) << 3;   // 32 thread-cols

    const float* Xb = X + (size_t)bb * CI * NPIX;
    const float* Ab = g_A + (size_t)bb * CI * CI;

    float acc[8][8];
#pragma unroll
    for (int i = 0; i < 8; i++)
#pragma unroll
        for (int j = 0; j < 8; j++) acc[i][j] = 0.f;

    for (int kc = 0; kc < 8; kc++) {
        float aBuf[4];
        float4 xBuf[2];
#pragma unroll
        for (int i = 0; i < 4; i++) {
            int li = t + i * 512;
            int r = li >> 4, kk = li & 15;
            aBuf[i] = Ab[r * CI + kc * 16 + kk];
        }
#pragma unroll
        for (int i = 0; i < 2; i++) {
            int li = t + i * 512;
            int row = li >> 6, c4 = li & 63;
            xBuf[i] = *(const float4*)(Xb + (size_t)(kc * 16 + row) * NPIX + n0 + c4 * 4);
        }
        __syncthreads();
#pragma unroll
        for (int i = 0; i < 4; i++) {
            int li = t + i * 512;
            int r = li >> 4, kk = li & 15;
            sAT[kk][r] = aBuf[i];
        }
#pragma unroll
        for (int i = 0; i < 2; i++) {
            int li = t + i * 512;
            int row = li >> 6, c4 = li & 63;
            *(float4*)&sX[row][c4 * 4] = xBuf[i];
        }
        __syncthreads();

#pragma unroll 4
        for (int k = 0; k < 16; k++) {
            float4 a0 = *(const float4*)&sAT[k][tr];
            float4 a1 = *(const float4*)&sAT[k][tr + 4];
            float4 b0 = *(const float4*)&sX[k][tcn];
            float4 b1 = *(const float4*)&sX[k][tcn + 4];
            float a[8] = {a0.x, a0.y, a0.z, a0.w, a1.x, a1.y, a1.z, a1.w};
            float b[8] = {b0.x, b0.y, b0.z, b0.w, b1.x, b1.y, b1.z, b1.w};
#pragma unroll
            for (int i = 0; i < 8; i++)
#pragma unroll
                for (int j = 0; j < 8; j++) acc[i][j] += a[i] * b[j];
        }
    }

#pragma unroll
    for (int i = 0; i < 8; i++) {
        float bias = g_bvec[bb * CI + tr + i];
        float4 o0, o1;
        o0.x = acc[i][0] + bias; o0.y = acc[i][1] + bias;
        o0.z = acc[i][2] + bias; o0.w = acc[i][3] + bias;
        o1.x = acc[i][4] + bias; o1.y = acc[i][5] + bias;
        o1.z = acc[i][6] + bias; o1.w = acc[i][7] + bias;
        float* dst = Z + (size_t)bb * CI * NPIX + (size_t)(tr + i) * NPIX + n0 + tcn;
        *(float4*)(dst)     = o0;
        *(float4*)(dst + 4) = o1;
    }
}

// =====================================================================
extern "C" void kernel_launch(void* const* d_in, const int* in_sizes, int n_in,
                              void* d_out, int out_size)
{
    (void)in_sizes; (void)n_in; (void)out_size;
    const float* x        = (const float*)d_in[0];
    const float* theta_w  = (const float*)d_in[1];
    const float* theta_b  = (const float*)d_in[2];
    const float* phi_w    = (const float*)d_in[3];
    const float* phi_b    = (const float*)d_in[4];
    const float* g_w      = (const float*)d_in[5];
    const float* g_b      = (const float*)d_in[6];
    const float* W_w      = (const float*)d_in[7];
    const float* W_b      = (const float*)d_in[8];
    const float* bn_gamma = (const float*)d_in[9];
    const float* bn_beta  = (const float*)d_in[10];
    const float* bn_mean  = (const float*)d_in[11];
    const float* bn_var   = (const float*)d_in[12];
    float* out = (float*)d_out;

    const int smem_chain = 3 * CI * PAD * (int)sizeof(float);  // 202752 B
    cudaFuncSetAttribute(chain_kernel,
                         cudaFuncAttributeMaxDynamicSharedMemorySize, smem_chain);

    gram_kernel<<<dim3(KSPLIT, NB), 256>>>(x);
    chain_kernel<<<NB, 256, smem_chain>>>(theta_w, theta_b, phi_w, phi_b,
                                          g_w, g_b, W_w, W_b,
                                          bn_gamma, bn_beta, bn_mean, bn_var);
    apply_kernel<<<dim3(NPIX / 256, NB), 512>>>(x, out);
}